// round 1
// baseline (speedup 1.0000x reference)
#include <cuda_runtime.h>
#include <math.h>

#define BEPS 1e-5f
#define NB 4096

// Scratch (allocation-free): z (4096x256), up (4096x6400)
__device__ float z_g[NB * 256];
__device__ float up_g[(size_t)NB * 6400];

// ---------------------------------------------------------------------------
// Kernel 1: encoder + prototype stage. One block per image, 256 threads.
// ---------------------------------------------------------------------------
__global__ __launch_bounds__(256) void enc_kernel(
    const float* __restrict__ x,
    const float* __restrict__ w1, const float* __restrict__ b1,
    const float* __restrict__ w2, const float* __restrict__ b2,
    const float* __restrict__ g2, const float* __restrict__ bt2,
    const float* __restrict__ w3, const float* __restrict__ b3,
    const float* __restrict__ proto,
    float* __restrict__ out_minD)
{
    __shared__ float xs[784];        // 28x28 input
    __shared__ float h1s[8 * 196];   // 8 x 14x14
    __shared__ float h2s[16 * 49];   // 16 x 7x7
    __shared__ float h3s[256 * 25];  // 256 x 5x5, [d][pos]
    __shared__ float x2s[25];
    __shared__ float as_[512];       // activations -> softmax weights
    __shared__ float red[256];

    const int b = blockIdx.x;
    const int t = threadIdx.x;

    // load input image
    const float* xb = x + b * 784;
    for (int i = t; i < 784; i += 256) xs[i] = xb[i];
    __syncthreads();

    // conv1: 1 -> 8, k3 s2 p1, 28->14, bias+relu
    for (int idx = t; idx < 1568; idx += 256) {
        int o = idx / 196, r = idx % 196, i = r / 14, j = r % 14;
        float acc = b1[o];
        #pragma unroll
        for (int ky = 0; ky < 3; ky++) {
            int y = 2 * i - 1 + ky;
            if ((unsigned)y >= 28u) continue;
            #pragma unroll
            for (int kx = 0; kx < 3; kx++) {
                int xx = 2 * j - 1 + kx;
                if ((unsigned)xx >= 28u) continue;
                acc += xs[y * 28 + xx] * w1[o * 9 + ky * 3 + kx];
            }
        }
        h1s[idx] = fmaxf(acc, 0.f);
    }
    __syncthreads();

    // conv2: 8 -> 16, k3 s2 p1, 14->7, bias+BN+relu
    {
        const float rs = rsqrtf(1.f + BEPS);
        for (int idx = t; idx < 784; idx += 256) {
            int o = idx / 49, r = idx % 49, i = r / 7, j = r % 7;
            float acc = 0.f;
            for (int c = 0; c < 8; c++) {
                #pragma unroll
                for (int ky = 0; ky < 3; ky++) {
                    int y = 2 * i - 1 + ky;
                    if ((unsigned)y >= 14u) continue;
                    #pragma unroll
                    for (int kx = 0; kx < 3; kx++) {
                        int xx = 2 * j - 1 + kx;
                        if ((unsigned)xx >= 14u) continue;
                        acc += h1s[c * 196 + y * 14 + xx] * w2[((o * 8 + c) * 3 + ky) * 3 + kx];
                    }
                }
            }
            float s = g2[o] * rs;
            h2s[idx] = fmaxf((acc + b2[o]) * s + bt2[o], 0.f);
        }
    }
    __syncthreads();

    // conv3: 16 -> 256, k3 s1 p0, 7->5, bias+relu. Thread t owns channel t.
    {
        float acc[25];
        #pragma unroll
        for (int p = 0; p < 25; p++) acc[p] = 0.f;
        const float* wrow = w3 + t * 144;
        for (int c = 0; c < 16; c++) {
            #pragma unroll
            for (int ky = 0; ky < 3; ky++) {
                #pragma unroll
                for (int kx = 0; kx < 3; kx++) {
                    float wv = wrow[c * 9 + ky * 3 + kx];
                    const float* hp = &h2s[c * 49 + ky * 7 + kx];
                    #pragma unroll
                    for (int i = 0; i < 5; i++)
                        #pragma unroll
                        for (int j = 0; j < 5; j++)
                            acc[i * 5 + j] += wv * hp[i * 7 + j];
                }
            }
        }
        float bb = b3[t];
        #pragma unroll
        for (int p = 0; p < 25; p++) h3s[t * 25 + p] = fmaxf(acc[p] + bb, 0.f);
    }
    __syncthreads();

    // per-position squared norm of h3
    if (t < 25) {
        float s = 0.f;
        for (int d = 0; d < 256; d++) {
            float v = h3s[d * 25 + t];
            s += v * v;
        }
        x2s[t] = s;
    }
    __syncthreads();

    // prototype distances: thread t handles prototypes t and t+256
    {
        float a0[25], a1[25];
        #pragma unroll
        for (int p = 0; p < 25; p++) { a0[p] = 0.f; a1[p] = 0.f; }
        float pp0 = 0.f, pp1 = 0.f;
        const float* pr0 = proto + (size_t)t * 256;
        const float* pr1 = proto + (size_t)(t + 256) * 256;
        for (int d = 0; d < 256; d++) {
            const float* hp = &h3s[d * 25];
            float v0 = pr0[d], v1 = pr1[d];
            pp0 += v0 * v0;
            pp1 += v1 * v1;
            #pragma unroll
            for (int p = 0; p < 25; p++) {
                float hv = hp[p];
                a0[p] += v0 * hv;
                a1[p] += v1 * hv;
            }
        }
        float m0 = 3.0e38f, m1 = 3.0e38f;
        #pragma unroll
        for (int p = 0; p < 25; p++) {
            float d0 = fmaxf(x2s[p] - 2.f * a0[p] + pp0, 0.f);
            float d1 = fmaxf(x2s[p] - 2.f * a1[p] + pp1, 0.f);
            m0 = fminf(m0, d0);
            m1 = fminf(m1, d1);
        }
        out_minD[(size_t)b * 512 + t] = m0;
        out_minD[(size_t)b * 512 + t + 256] = m1;
        as_[t] = -m0;
        as_[t + 256] = -m1;
    }
    __syncthreads();

    // softmax over 512 prototypes
    float lm = fmaxf(as_[t], as_[t + 256]);
    red[t] = lm;
    __syncthreads();
    for (int s = 128; s > 0; s >>= 1) {
        if (t < s) red[t] = fmaxf(red[t], red[t + s]);
        __syncthreads();
    }
    float amax = red[0];
    __syncthreads();
    float e0 = expf(as_[t] - amax);
    float e1 = expf(as_[t + 256] - amax);
    red[t] = e0 + e1;
    __syncthreads();
    for (int s = 128; s > 0; s >>= 1) {
        if (t < s) red[t] += red[t + s];
        __syncthreads();
    }
    float inv = 1.f / red[0];
    __syncthreads();
    as_[t] = e0 * inv;
    as_[t + 256] = e1 * inv;
    __syncthreads();

    // z[b, d=t] = sum_p w[p] * proto[p, t]  (coalesced proto column reads)
    {
        float acc = 0.f;
        for (int p = 0; p < 512; p++) acc += as_[p] * proto[(size_t)p * 256 + t];
        z_g[(size_t)b * 256 + t] = acc;
    }
}

// ---------------------------------------------------------------------------
// Kernel 2: up-projection GEMM  up[b, o*25+pos] = relu(BN(z[b,:] . wup[:, o, pos]))
// M=4096, N=6400, K=256. 64x64 tile, 4x4 per thread.
// ---------------------------------------------------------------------------
__global__ __launch_bounds__(256) void up_kernel(
    const float* __restrict__ wup, const float* __restrict__ bup,
    const float* __restrict__ gup, const float* __restrict__ btup)
{
    __shared__ float As[16][64];  // [k][m]
    __shared__ float Bs[16][64];  // [k][n]

    const int bn = blockIdx.x * 64;
    const int bm = blockIdx.y * 64;
    const int t = threadIdx.x;
    const int tx = t & 15, ty = t >> 4;

    float acc[4][4];
    #pragma unroll
    for (int i = 0; i < 4; i++)
        #pragma unroll
        for (int j = 0; j < 4; j++) acc[i][j] = 0.f;

    for (int k0 = 0; k0 < 256; k0 += 16) {
        {
            int r = t >> 2, kk = (t & 3) * 4;
            float4 v = *(const float4*)(&z_g[(size_t)(bm + r) * 256 + k0 + kk]);
            As[kk + 0][r] = v.x;
            As[kk + 1][r] = v.y;
            As[kk + 2][r] = v.z;
            As[kk + 3][r] = v.w;
        }
        {
            int kk = t >> 4, n4 = (t & 15) * 4;
            float4 v = *(const float4*)(&wup[(size_t)(k0 + kk) * 6400 + bn + n4]);
            *(float4*)&Bs[kk][n4] = v;
        }
        __syncthreads();
        #pragma unroll
        for (int kk = 0; kk < 16; kk++) {
            float4 av = *(const float4*)&As[kk][ty * 4];
            float4 bv = *(const float4*)&Bs[kk][tx * 4];
            float a[4] = {av.x, av.y, av.z, av.w};
            float bb[4] = {bv.x, bv.y, bv.z, bv.w};
            #pragma unroll
            for (int i = 0; i < 4; i++)
                #pragma unroll
                for (int j = 0; j < 4; j++) acc[i][j] += a[i] * bb[j];
        }
        __syncthreads();
    }

    const float rs = rsqrtf(1.f + BEPS);
    #pragma unroll
    for (int j = 0; j < 4; j++) {
        int n = bn + tx * 4 + j;
        int o = n / 25;
        float s = gup[o] * rs;
        float bias = bup[o] * s + btup[o];
        #pragma unroll
        for (int i = 0; i < 4; i++) {
            int m = bm + ty * 4 + i;
            up_g[(size_t)m * 6400 + n] = fmaxf(acc[i][j] * s + bias, 0.f);
        }
    }
}

// ---------------------------------------------------------------------------
// Kernel 3: decoder (transposed convs). 4 images per block, 256 threads.
// smem: ups[4][6400] | wts[32*144] | d1s[4][784] | d2s[4][1568] | wd2s | wd3s
// ---------------------------------------------------------------------------
__global__ __launch_bounds__(256) void dec_kernel(
    const float* __restrict__ wd1, const float* __restrict__ bd1,
    const float* __restrict__ gd1, const float* __restrict__ btd1,
    const float* __restrict__ wd2, const float* __restrict__ bd2,
    const float* __restrict__ gd2, const float* __restrict__ btd2,
    const float* __restrict__ wd3, const float* __restrict__ bd3,
    float* __restrict__ out)
{
    extern __shared__ float sm[];
    float* ups  = sm;                 // 25600
    float* wts  = ups + 25600;        // 4608
    float* d1s  = wts + 4608;         // 3136
    float* d2s  = d1s + 3136;         // 6272
    float* wd2s = d2s + 6272;         // 1152
    float* wd3s = wd2s + 1152;        // 72

    const int t = threadIdx.x;
    const int b0 = blockIdx.x * 4;
    const float rs = rsqrtf(1.f + BEPS);

    for (int i = t; i < 25600; i += 256) ups[i] = up_g[(size_t)b0 * 6400 + i];
    for (int i = t; i < 1152; i += 256) wd2s[i] = wd2[i];
    if (t < 72) wd3s[t] = wd3[t];

    // ---- d1: conv_t 256->16, k3 s1 p0, 5->7. thread = (pos<49, og<4); 4 imgs x 4 oc
    const int pos = t % 49;
    const int og = t / 49;          // valid for t < 196
    const int oi = pos / 7, oj = pos % 7;
    const int y0 = max(oi - 2, 0), y1 = min(oi, 4);
    const int x0 = max(oj - 2, 0), x1 = min(oj, 4);

    float acc[4][4];
    #pragma unroll
    for (int a = 0; a < 4; a++)
        #pragma unroll
        for (int o = 0; o < 4; o++) acc[a][o] = 0.f;

    for (int c0 = 0; c0 < 256; c0 += 32) {
        __syncthreads();
        // stage wd1 chunk transposed: wts[c*144 + tap*16 + o] = wd1[(c0+c)*144 + o*9 + tap]
        for (int i = t; i < 4608; i += 256) {
            int c = i / 144, r = i % 144, o = r / 9, tap = r % 9;
            wts[c * 144 + tap * 16 + o] = wd1[(size_t)(c0 + c) * 144 + o * 9 + tap];
        }
        __syncthreads();
        if (t < 196) {
            for (int c = 0; c < 32; c++) {
                int cb = (c0 + c) * 25;
                const float* wb = &wts[c * 144];
                for (int y = y0; y <= y1; y++) {
                    int ki = oi - y;
                    for (int xx = x0; xx <= x1; xx++) {
                        int kj = oj - xx;
                        float4 w4 = *(const float4*)&wb[(ki * 3 + kj) * 16 + og * 4];
                        float u0 = ups[0 * 6400 + cb + y * 5 + xx];
                        float u1 = ups[1 * 6400 + cb + y * 5 + xx];
                        float u2 = ups[2 * 6400 + cb + y * 5 + xx];
                        float u3 = ups[3 * 6400 + cb + y * 5 + xx];
                        acc[0][0] += u0 * w4.x; acc[0][1] += u0 * w4.y;
                        acc[0][2] += u0 * w4.z; acc[0][3] += u0 * w4.w;
                        acc[1][0] += u1 * w4.x; acc[1][1] += u1 * w4.y;
                        acc[1][2] += u1 * w4.z; acc[1][3] += u1 * w4.w;
                        acc[2][0] += u2 * w4.x; acc[2][1] += u2 * w4.y;
                        acc[2][2] += u2 * w4.z; acc[2][3] += u2 * w4.w;
                        acc[3][0] += u3 * w4.x; acc[3][1] += u3 * w4.y;
                        acc[3][2] += u3 * w4.z; acc[3][3] += u3 * w4.w;
                    }
                }
            }
        }
    }
    if (t < 196) {
        #pragma unroll
        for (int oo = 0; oo < 4; oo++) {
            int o = og * 4 + oo;
            float s = gd1[o] * rs;
            float bias = bd1[o] * s + btd1[o];
            #pragma unroll
            for (int a = 0; a < 4; a++)
                d1s[a * 784 + o * 49 + pos] = fmaxf(acc[a][oo] * s + bias, 0.f);
        }
    }
    __syncthreads();

    // ---- d2: conv_t 16->8, k3 s2 p1 op1, 7->14. thread = pos<196; 4 imgs x 8 oc
    if (t < 196) {
        float acc2[4][8];
        #pragma unroll
        for (int a = 0; a < 4; a++)
            #pragma unroll
            for (int o = 0; o < 8; o++) acc2[a][o] = 0.f;
        int i = t / 14, j = t % 14;
        int ylo = i / 2, yhi = min((i + 1) / 2, 6);
        int xlo = j / 2, xhi = min((j + 1) / 2, 6);
        for (int c = 0; c < 16; c++) {
            for (int y = ylo; y <= yhi; y++) {
                int ki = i - 2 * y + 1;
                for (int xx = xlo; xx <= xhi; xx++) {
                    int kj = j - 2 * xx + 1;
                    float u0 = d1s[0 * 784 + c * 49 + y * 7 + xx];
                    float u1 = d1s[1 * 784 + c * 49 + y * 7 + xx];
                    float u2 = d1s[2 * 784 + c * 49 + y * 7 + xx];
                    float u3 = d1s[3 * 784 + c * 49 + y * 7 + xx];
                    #pragma unroll
                    for (int o = 0; o < 8; o++) {
                        float wv = wd2s[((c * 8 + o) * 3 + ki) * 3 + kj];
                        acc2[0][o] += u0 * wv;
                        acc2[1][o] += u1 * wv;
                        acc2[2][o] += u2 * wv;
                        acc2[3][o] += u3 * wv;
                    }
                }
            }
        }
        #pragma unroll
        for (int o = 0; o < 8; o++) {
            float s = gd2[o] * rs;
            float bias = bd2[o] * s + btd2[o];
            #pragma unroll
            for (int a = 0; a < 4; a++)
                d2s[a * 1568 + o * 196 + t] = fmaxf(acc2[a][o] * s + bias, 0.f);
        }
    }
    __syncthreads();

    // ---- d3: conv_t 8->1, k3 s2 p1 op1, 14->28, sigmoid
    const float bb3 = bd3[0];
    for (int idx = t; idx < 3136; idx += 256) {
        int a = idx / 784, p = idx % 784, i = p / 28, j = p % 28;
        int ylo = i / 2, yhi = min((i + 1) / 2, 13);
        int xlo = j / 2, xhi = min((j + 1) / 2, 13);
        float acc3 = bb3;
        for (int c = 0; c < 8; c++) {
            for (int y = ylo; y <= yhi; y++) {
                int ki = i - 2 * y + 1;
                for (int xx = xlo; xx <= xhi; xx++) {
                    int kj = j - 2 * xx + 1;
                    acc3 += d2s[a * 1568 + c * 196 + y * 14 + xx] * wd3s[c * 9 + ki * 3 + kj];
                }
            }
        }
        out[(size_t)(b0 + a) * 784 + p] = 1.f / (1.f + expf(-acc3));
    }
}

// ---------------------------------------------------------------------------
extern "C" void kernel_launch(void* const* d_in, const int* in_sizes, int n_in,
                              void* d_out, int out_size)
{
    const float* x     = (const float*)d_in[0];
    const float* w1    = (const float*)d_in[1];
    const float* b1    = (const float*)d_in[2];
    const float* w2    = (const float*)d_in[3];
    const float* b2    = (const float*)d_in[4];
    const float* g2    = (const float*)d_in[5];
    const float* bt2   = (const float*)d_in[6];
    const float* w3    = (const float*)d_in[7];
    const float* b3    = (const float*)d_in[8];
    const float* proto = (const float*)d_in[9];
    const float* wup   = (const float*)d_in[10];
    const float* bup   = (const float*)d_in[11];
    const float* gup   = (const float*)d_in[12];
    const float* btup  = (const float*)d_in[13];
    const float* wd1   = (const float*)d_in[14];
    const float* bd1   = (const float*)d_in[15];
    const float* gd1   = (const float*)d_in[16];
    const float* btd1  = (const float*)d_in[17];
    const float* wd2   = (const float*)d_in[18];
    const float* bd2   = (const float*)d_in[19];
    const float* gd2   = (const float*)d_in[20];
    const float* btd2  = (const float*)d_in[21];
    const float* wd3   = (const float*)d_in[22];
    const float* bd3   = (const float*)d_in[23];

    float* out  = (float*)d_out;                 // (4096,1,28,28)
    float* minD = out + (size_t)NB * 784;        // (4096,512)

    enc_kernel<<<NB, 256>>>(x, w1, b1, w2, b2, g2, bt2, w3, b3, proto, minD);

    dim3 gu(6400 / 64, NB / 64);
    up_kernel<<<gu, 256>>>(wup, bup, gup, btup);

    size_t smem = (size_t)(25600 + 4608 + 3136 + 6272 + 1152 + 72) * sizeof(float); // 163,360 B
    cudaFuncSetAttribute(dec_kernel, cudaFuncAttributeMaxDynamicSharedMemorySize, (int)smem);
    dec_kernel<<<NB / 4, 256, smem>>>(wd1, bd1, gd1, btd1,
                                      wd2, bd2, gd2, btd2,
                                      wd3, bd3, out);
}

// round 2
// speedup vs baseline: 1.6208x; 1.6208x over previous
#include <cuda_runtime.h>
#include <math.h>

#define BEPS 1e-5f
#define NB 4096

// ---------------- scratch (allocation-free) ----------------
__device__ float h2_g[NB * 784];
__device__ float h3_g[(size_t)NB * 6400];
__device__ float w_g[NB * 512];
__device__ float z_g[NB * 256];
__device__ float up_g[(size_t)NB * 6400];
__device__ float protoT_g[257 * 512];   // [d][p], padded one extra d row
__device__ float w3t_g[256 * 144];      // [(c*9+tap)][oc]
__device__ float wd1t_g[256 * 144];     // [c][tap*16+o]

// ---------------- packed fp32x2 helpers (sm_100+) ----------------
static __device__ __forceinline__ unsigned long long ffma2(
    unsigned long long a, unsigned long long b, unsigned long long c) {
    unsigned long long d;
    asm("fma.rn.f32x2 %0, %1, %2, %3;" : "=l"(d) : "l"(a), "l"(b), "l"(c));
    return d;
}
static __device__ __forceinline__ unsigned long long pack2(float x, float y) {
    unsigned long long r;
    asm("mov.b64 %0, {%1, %2};" : "=l"(r) : "f"(x), "f"(y));
    return r;
}
static __device__ __forceinline__ float2 unpack2(unsigned long long v) {
    float2 r;
    asm("mov.b64 {%0, %1}, %2;" : "=f"(r.x), "=f"(r.y) : "l"(v));
    return r;
}

// ---------------------------------------------------------------------------
// prep: weight transposes (runs every replay; deterministic)
// ---------------------------------------------------------------------------
__global__ void prep_kernel(const float* __restrict__ proto,
                            const float* __restrict__ w3,
                            const float* __restrict__ wd1)
{
    int stride = gridDim.x * blockDim.x;
    int tid = blockIdx.x * blockDim.x + threadIdx.x;
    // protoT[d*512+p] = proto[p*256+d]
    for (int i = tid; i < 512 * 256; i += stride) {
        int d = i >> 9, p = i & 511;
        protoT_g[i] = proto[p * 256 + d];
    }
    // w3t[(c*9+tap)*256 + o] = w3[o*144 + c*9 + tap]
    for (int i = tid; i < 256 * 144; i += stride) {
        int o = i & 255, ct = i >> 8;
        int c = ct / 9, tap = ct - c * 9;
        w3t_g[i] = w3[o * 144 + c * 9 + tap];
    }
    // wd1t[c*144 + tap*16 + o] = wd1[c*144 + o*9 + tap]
    for (int i = tid; i < 256 * 144; i += stride) {
        int o = i & 15, ct = i >> 4;
        int c = ct / 9, tap = ct - c * 9;
        wd1t_g[c * 144 + tap * 16 + o] = wd1[c * 144 + o * 9 + tap];
    }
}

// ---------------------------------------------------------------------------
// enc12: conv1 + conv2, one block per image
// ---------------------------------------------------------------------------
__global__ __launch_bounds__(128) void enc12_kernel(
    const float* __restrict__ x,
    const float* __restrict__ w1, const float* __restrict__ b1,
    const float* __restrict__ w2, const float* __restrict__ b2,
    const float* __restrict__ g2, const float* __restrict__ bt2)
{
    __shared__ float xs[784];
    __shared__ float h1s[8 * 196];
    const int b = blockIdx.x;
    const int t = threadIdx.x;

    const float* xb = x + b * 784;
    for (int i = t; i < 784; i += 128) xs[i] = xb[i];
    __syncthreads();

    for (int idx = t; idx < 1568; idx += 128) {
        int o = idx / 196, r = idx % 196, i = r / 14, j = r % 14;
        float acc = b1[o];
        #pragma unroll
        for (int ky = 0; ky < 3; ky++) {
            int y = 2 * i - 1 + ky;
            if ((unsigned)y >= 28u) continue;
            #pragma unroll
            for (int kx = 0; kx < 3; kx++) {
                int xx = 2 * j - 1 + kx;
                if ((unsigned)xx >= 28u) continue;
                acc += xs[y * 28 + xx] * w1[o * 9 + ky * 3 + kx];
            }
        }
        h1s[idx] = fmaxf(acc, 0.f);
    }
    __syncthreads();

    const float rs = rsqrtf(1.f + BEPS);
    for (int idx = t; idx < 784; idx += 128) {
        int o = idx / 49, r = idx % 49, i = r / 7, j = r % 7;
        float acc = 0.f;
        for (int c = 0; c < 8; c++) {
            #pragma unroll
            for (int ky = 0; ky < 3; ky++) {
                int y = 2 * i - 1 + ky;
                if ((unsigned)y >= 14u) continue;
                #pragma unroll
                for (int kx = 0; kx < 3; kx++) {
                    int xx = 2 * j - 1 + kx;
                    if ((unsigned)xx >= 14u) continue;
                    acc += h1s[c * 196 + y * 14 + xx] * w2[((o * 8 + c) * 3 + ky) * 3 + kx];
                }
            }
        }
        float s = g2[o] * rs;
        h2_g[b * 784 + idx] = fmaxf((acc + b2[o]) * s + bt2[o], 0.f);
    }
}

// ---------------------------------------------------------------------------
// conv3: 16 -> 256, k3 s1 p0, 7->5. One block per image, thread = out channel.
// 49 h-values per input channel held in registers: 225 FMA per 58 loads.
// ---------------------------------------------------------------------------
__global__ __launch_bounds__(256, 2) void conv3_kernel(const float* __restrict__ b3)
{
    __shared__ float h2s[784];
    __shared__ float h3s[6400];
    const int b = blockIdx.x;
    const int t = threadIdx.x;

    for (int i = t; i < 784; i += 256) h2s[i] = h2_g[b * 784 + i];
    __syncthreads();

    float acc[25];
    #pragma unroll
    for (int p = 0; p < 25; p++) acc[p] = 0.f;

    for (int c = 0; c < 16; c++) {
        float w[9];
        #pragma unroll
        for (int tap = 0; tap < 9; tap++) w[tap] = w3t_g[(c * 9 + tap) * 256 + t];
        float h[49];
        #pragma unroll
        for (int i = 0; i < 49; i++) h[i] = h2s[c * 49 + i];
        #pragma unroll
        for (int ky = 0; ky < 3; ky++)
            #pragma unroll
            for (int kx = 0; kx < 3; kx++) {
                float wv = w[ky * 3 + kx];
                #pragma unroll
                for (int i = 0; i < 5; i++)
                    #pragma unroll
                    for (int j = 0; j < 5; j++)
                        acc[i * 5 + j] += wv * h[(i + ky) * 7 + (j + kx)];
            }
    }
    float bb = b3[t];
    #pragma unroll
    for (int p = 0; p < 25; p++) h3s[t * 25 + p] = fmaxf(acc[p] + bb, 0.f);
    __syncthreads();

    for (int i = t; i < 6400; i += 256) h3_g[(size_t)b * 6400 + i] = h3s[i];
}

// ---------------------------------------------------------------------------
// proto: distances + min + softmax. Block = image, 512 threads = 512 prototypes.
// Packed f32x2 accumulators; h-pairs via LDS.128 from padded smem.
// ---------------------------------------------------------------------------
__global__ __launch_bounds__(512) void proto_kernel(float* __restrict__ out_minD)
{
    __shared__ __align__(16) float h3s[256 * 28];
    __shared__ float x2s[25];
    __shared__ float red[32];

    const int b = blockIdx.x;
    const int t = threadIdx.x;

    for (int i = t; i < 6400; i += 512) {
        int d = i / 25, p = i - d * 25;
        h3s[d * 28 + p] = h3_g[(size_t)b * 6400 + i];
    }
    __syncthreads();
    if (t < 25) {
        float s = 0.f;
        for (int d = 0; d < 256; d++) {
            float v = h3s[d * 28 + t];
            s += v * v;
        }
        x2s[t] = s;
    }
    __syncthreads();

    unsigned long long acc[12];
    #pragma unroll
    for (int k = 0; k < 12; k++) acc[k] = 0ull;
    float acc24 = 0.f, pp = 0.f;

    #pragma unroll 2
    for (int d = 0; d < 256; d++) {
        float pv = protoT_g[d * 512 + t];
        unsigned long long pv2 = pack2(pv, pv);
        pp = fmaf(pv, pv, pp);
        const ulonglong2* hp = (const ulonglong2*)&h3s[d * 28];
        ulonglong2 q0 = hp[0], q1 = hp[1], q2 = hp[2];
        ulonglong2 q3 = hp[3], q4 = hp[4], q5 = hp[5];
        acc[0]  = ffma2(q0.x, pv2, acc[0]);
        acc[1]  = ffma2(q0.y, pv2, acc[1]);
        acc[2]  = ffma2(q1.x, pv2, acc[2]);
        acc[3]  = ffma2(q1.y, pv2, acc[3]);
        acc[4]  = ffma2(q2.x, pv2, acc[4]);
        acc[5]  = ffma2(q2.y, pv2, acc[5]);
        acc[6]  = ffma2(q3.x, pv2, acc[6]);
        acc[7]  = ffma2(q3.y, pv2, acc[7]);
        acc[8]  = ffma2(q4.x, pv2, acc[8]);
        acc[9]  = ffma2(q4.y, pv2, acc[9]);
        acc[10] = ffma2(q5.x, pv2, acc[10]);
        acc[11] = ffma2(q5.y, pv2, acc[11]);
        acc24 = fmaf(pv, h3s[d * 28 + 24], acc24);
    }

    float m = 3.0e38f;
    #pragma unroll
    for (int k = 0; k < 12; k++) {
        float2 f = unpack2(acc[k]);
        float d0 = fmaxf(x2s[2 * k]     - 2.f * f.x + pp, 0.f);
        float d1 = fmaxf(x2s[2 * k + 1] - 2.f * f.y + pp, 0.f);
        m = fminf(m, fminf(d0, d1));
    }
    m = fminf(m, fmaxf(x2s[24] - 2.f * acc24 + pp, 0.f));

    out_minD[(size_t)b * 512 + t] = m;

    // softmax over 512 prototypes
    const int lane = t & 31, wid = t >> 5;
    float a = -m;
    float v = a;
    #pragma unroll
    for (int off = 16; off; off >>= 1) v = fmaxf(v, __shfl_xor_sync(0xffffffffu, v, off));
    if (!lane) red[wid] = v;
    __syncthreads();
    if (t == 0) {
        float r = red[0];
        for (int i = 1; i < 16; i++) r = fmaxf(r, red[i]);
        red[16] = r;
    }
    __syncthreads();
    float amax = red[16];
    float e = expf(a - amax);
    float sv = e;
    #pragma unroll
    for (int off = 16; off; off >>= 1) sv += __shfl_xor_sync(0xffffffffu, sv, off);
    __syncthreads();
    if (!lane) red[wid] = sv;
    __syncthreads();
    if (t == 0) {
        float r = 0.f;
        for (int i = 0; i < 16; i++) r += red[i];
        red[16] = r;
    }
    __syncthreads();
    w_g[(size_t)b * 512 + t] = e * (1.f / red[16]);
}

// ---------------------------------------------------------------------------
// Tiled GEMM 128x64, micro 8x4 with f32x2 (m-pairs). C = A(MxK) * B(KxN).
// ---------------------------------------------------------------------------
// z: A=w_g (4096x512), B=proto (512x256)        -> z_g
// up: A=z_g (4096x256), B=wup (256x6400), BN+relu -> up_g
__global__ __launch_bounds__(256) void z_gemm_kernel(const float* __restrict__ proto)
{
    __shared__ __align__(16) float As[16][128];
    __shared__ __align__(16) float Bs[16][64];
    const int bn = blockIdx.x * 64;
    const int bm = blockIdx.y * 128;
    const int t = threadIdx.x;
    const int tx = t & 15, ty = t >> 4;

    unsigned long long acc[4][4];
    #pragma unroll
    for (int i = 0; i < 4; i++)
        #pragma unroll
        for (int j = 0; j < 4; j++) acc[i][j] = 0ull;

    for (int k0 = 0; k0 < 512; k0 += 16) {
        #pragma unroll
        for (int s = t; s < 512; s += 256) {
            int r = s >> 2, kq = (s & 3) << 2;
            float4 v = *(const float4*)&w_g[(size_t)(bm + r) * 512 + k0 + kq];
            As[kq + 0][r] = v.x; As[kq + 1][r] = v.y;
            As[kq + 2][r] = v.z; As[kq + 3][r] = v.w;
        }
        {
            int kk = t >> 4, n4 = (t & 15) << 2;
            *(float4*)&Bs[kk][n4] = *(const float4*)&proto[(size_t)(k0 + kk) * 256 + bn + n4];
        }
        __syncthreads();
        #pragma unroll
        for (int kk = 0; kk < 16; kk++) {
            ulonglong2 a01 = *(const ulonglong2*)&As[kk][ty * 8];
            ulonglong2 a23 = *(const ulonglong2*)&As[kk][ty * 8 + 4];
            float4 bv = *(const float4*)&Bs[kk][tx * 4];
            unsigned long long bd0 = pack2(bv.x, bv.x), bd1 = pack2(bv.y, bv.y);
            unsigned long long bd2 = pack2(bv.z, bv.z), bd3 = pack2(bv.w, bv.w);
            acc[0][0] = ffma2(a01.x, bd0, acc[0][0]); acc[0][1] = ffma2(a01.x, bd1, acc[0][1]);
            acc[0][2] = ffma2(a01.x, bd2, acc[0][2]); acc[0][3] = ffma2(a01.x, bd3, acc[0][3]);
            acc[1][0] = ffma2(a01.y, bd0, acc[1][0]); acc[1][1] = ffma2(a01.y, bd1, acc[1][1]);
            acc[1][2] = ffma2(a01.y, bd2, acc[1][2]); acc[1][3] = ffma2(a01.y, bd3, acc[1][3]);
            acc[2][0] = ffma2(a23.x, bd0, acc[2][0]); acc[2][1] = ffma2(a23.x, bd1, acc[2][1]);
            acc[2][2] = ffma2(a23.x, bd2, acc[2][2]); acc[2][3] = ffma2(a23.x, bd3, acc[2][3]);
            acc[3][0] = ffma2(a23.y, bd0, acc[3][0]); acc[3][1] = ffma2(a23.y, bd1, acc[3][1]);
            acc[3][2] = ffma2(a23.y, bd2, acc[3][2]); acc[3][3] = ffma2(a23.y, bd3, acc[3][3]);
        }
        __syncthreads();
    }

    #pragma unroll
    for (int mp = 0; mp < 4; mp++) {
        int m0 = bm + ty * 8 + mp * 2;
        float2 f0 = unpack2(acc[mp][0]), f1 = unpack2(acc[mp][1]);
        float2 f2 = unpack2(acc[mp][2]), f3 = unpack2(acc[mp][3]);
        float4 r0 = make_float4(f0.x, f1.x, f2.x, f3.x);
        float4 r1 = make_float4(f0.y, f1.y, f2.y, f3.y);
        *(float4*)&z_g[(size_t)m0 * 256 + bn + tx * 4] = r0;
        *(float4*)&z_g[(size_t)(m0 + 1) * 256 + bn + tx * 4] = r1;
    }
}

__global__ __launch_bounds__(256) void up_gemm_kernel(
    const float* __restrict__ wup, const float* __restrict__ bup,
    const float* __restrict__ gup, const float* __restrict__ btup)
{
    __shared__ __align__(16) float As[16][128];
    __shared__ __align__(16) float Bs[16][64];
    const int bn = blockIdx.x * 64;
    const int bm = blockIdx.y * 128;
    const int t = threadIdx.x;
    const int tx = t & 15, ty = t >> 4;

    unsigned long long acc[4][4];
    #pragma unroll
    for (int i = 0; i < 4; i++)
        #pragma unroll
        for (int j = 0; j < 4; j++) acc[i][j] = 0ull;

    for (int k0 = 0; k0 < 256; k0 += 16) {
        #pragma unroll
        for (int s = t; s < 512; s += 256) {
            int r = s >> 2, kq = (s & 3) << 2;
            float4 v = *(const float4*)&z_g[(size_t)(bm + r) * 256 + k0 + kq];
            As[kq + 0][r] = v.x; As[kq + 1][r] = v.y;
            As[kq + 2][r] = v.z; As[kq + 3][r] = v.w;
        }
        {
            int kk = t >> 4, n4 = (t & 15) << 2;
            *(float4*)&Bs[kk][n4] = *(const float4*)&wup[(size_t)(k0 + kk) * 6400 + bn + n4];
        }
        __syncthreads();
        #pragma unroll
        for (int kk = 0; kk < 16; kk++) {
            ulonglong2 a01 = *(const ulonglong2*)&As[kk][ty * 8];
            ulonglong2 a23 = *(const ulonglong2*)&As[kk][ty * 8 + 4];
            float4 bv = *(const float4*)&Bs[kk][tx * 4];
            unsigned long long bd0 = pack2(bv.x, bv.x), bd1 = pack2(bv.y, bv.y);
            unsigned long long bd2 = pack2(bv.z, bv.z), bd3 = pack2(bv.w, bv.w);
            acc[0][0] = ffma2(a01.x, bd0, acc[0][0]); acc[0][1] = ffma2(a01.x, bd1, acc[0][1]);
            acc[0][2] = ffma2(a01.x, bd2, acc[0][2]); acc[0][3] = ffma2(a01.x, bd3, acc[0][3]);
            acc[1][0] = ffma2(a01.y, bd0, acc[1][0]); acc[1][1] = ffma2(a01.y, bd1, acc[1][1]);
            acc[1][2] = ffma2(a01.y, bd2, acc[1][2]); acc[1][3] = ffma2(a01.y, bd3, acc[1][3]);
            acc[2][0] = ffma2(a23.x, bd0, acc[2][0]); acc[2][1] = ffma2(a23.x, bd1, acc[2][1]);
            acc[2][2] = ffma2(a23.x, bd2, acc[2][2]); acc[2][3] = ffma2(a23.x, bd3, acc[2][3]);
            acc[3][0] = ffma2(a23.y, bd0, acc[3][0]); acc[3][1] = ffma2(a23.y, bd1, acc[3][1]);
            acc[3][2] = ffma2(a23.y, bd2, acc[3][2]); acc[3][3] = ffma2(a23.y, bd3, acc[3][3]);
        }
        __syncthreads();
    }

    const float rsc = rsqrtf(1.f + BEPS);
    float sc[4], bi[4];
    #pragma unroll
    for (int j = 0; j < 4; j++) {
        int n = bn + tx * 4 + j;
        int o = n / 25;
        sc[j] = gup[o] * rsc;
        bi[j] = bup[o] * sc[j] + btup[o];
    }
    #pragma unroll
    for (int mp = 0; mp < 4; mp++) {
        int m0 = bm + ty * 8 + mp * 2;
        float2 f0 = unpack2(acc[mp][0]), f1 = unpack2(acc[mp][1]);
        float2 f2 = unpack2(acc[mp][2]), f3 = unpack2(acc[mp][3]);
        float4 r0 = make_float4(fmaxf(f0.x * sc[0] + bi[0], 0.f), fmaxf(f1.x * sc[1] + bi[1], 0.f),
                                fmaxf(f2.x * sc[2] + bi[2], 0.f), fmaxf(f3.x * sc[3] + bi[3], 0.f));
        float4 r1 = make_float4(fmaxf(f0.y * sc[0] + bi[0], 0.f), fmaxf(f1.y * sc[1] + bi[1], 0.f),
                                fmaxf(f2.y * sc[2] + bi[2], 0.f), fmaxf(f3.y * sc[3] + bi[3], 0.f));
        *(float4*)&up_g[(size_t)m0 * 6400 + bn + tx * 4] = r0;
        *(float4*)&up_g[(size_t)(m0 + 1) * 6400 + bn + tx * 4] = r1;
    }
}

// ---------------------------------------------------------------------------
// dec: transposed convs. 4 images per block, 256 threads (unchanged, passing).
// ---------------------------------------------------------------------------
__global__ __launch_bounds__(256) void dec_kernel(
    const float* __restrict__ bd1,
    const float* __restrict__ gd1, const float* __restrict__ btd1,
    const float* __restrict__ wd2, const float* __restrict__ bd2,
    const float* __restrict__ gd2, const float* __restrict__ btd2,
    const float* __restrict__ wd3, const float* __restrict__ bd3,
    float* __restrict__ out)
{
    extern __shared__ float sm[];
    float* ups  = sm;                 // 25600
    float* wts  = ups + 25600;        // 4608
    float* d1s  = wts + 4608;         // 3136
    float* d2s  = d1s + 3136;         // 6272
    float* wd2s = d2s + 6272;         // 1152
    float* wd3s = wd2s + 1152;        // 72

    const int t = threadIdx.x;
    const int b0 = blockIdx.x * 4;
    const float rs = rsqrtf(1.f + BEPS);

    for (int i = t; i < 25600; i += 256) ups[i] = up_g[(size_t)b0 * 6400 + i];
    for (int i = t; i < 1152; i += 256) wd2s[i] = wd2[i];
    if (t < 72) wd3s[t] = wd3[t];

    const int pos = t % 49;
    const int og = t / 49;
    const int oi = pos / 7, oj = pos % 7;
    const int y0 = max(oi - 2, 0), y1 = min(oi, 4);
    const int x0 = max(oj - 2, 0), x1 = min(oj, 4);

    float acc[4][4];
    #pragma unroll
    for (int a = 0; a < 4; a++)
        #pragma unroll
        for (int o = 0; o < 4; o++) acc[a][o] = 0.f;

    for (int c0 = 0; c0 < 256; c0 += 32) {
        __syncthreads();
        for (int i = t; i < 4608; i += 256) wts[i] = wd1t_g[c0 * 144 + i];
        __syncthreads();
        if (t < 196) {
            for (int c = 0; c < 32; c++) {
                int cb = (c0 + c) * 25;
                const float* wb = &wts[c * 144];
                for (int y = y0; y <= y1; y++) {
                    int ki = oi - y;
                    for (int xx = x0; xx <= x1; xx++) {
                        int kj = oj - xx;
                        float4 w4 = *(const float4*)&wb[(ki * 3 + kj) * 16 + og * 4];
                        float u0 = ups[0 * 6400 + cb + y * 5 + xx];
                        float u1 = ups[1 * 6400 + cb + y * 5 + xx];
                        float u2 = ups[2 * 6400 + cb + y * 5 + xx];
                        float u3 = ups[3 * 6400 + cb + y * 5 + xx];
                        acc[0][0] += u0 * w4.x; acc[0][1] += u0 * w4.y;
                        acc[0][2] += u0 * w4.z; acc[0][3] += u0 * w4.w;
                        acc[1][0] += u1 * w4.x; acc[1][1] += u1 * w4.y;
                        acc[1][2] += u1 * w4.z; acc[1][3] += u1 * w4.w;
                        acc[2][0] += u2 * w4.x; acc[2][1] += u2 * w4.y;
                        acc[2][2] += u2 * w4.z; acc[2][3] += u2 * w4.w;
                        acc[3][0] += u3 * w4.x; acc[3][1] += u3 * w4.y;
                        acc[3][2] += u3 * w4.z; acc[3][3] += u3 * w4.w;
                    }
                }
            }
        }
    }
    if (t < 196) {
        #pragma unroll
        for (int oo = 0; oo < 4; oo++) {
            int o = og * 4 + oo;
            float s = gd1[o] * rs;
            float bias = bd1[o] * s + btd1[o];
            #pragma unroll
            for (int a = 0; a < 4; a++)
                d1s[a * 784 + o * 49 + pos] = fmaxf(acc[a][oo] * s + bias, 0.f);
        }
    }
    __syncthreads();

    if (t < 196) {
        float acc2[4][8];
        #pragma unroll
        for (int a = 0; a < 4; a++)
            #pragma unroll
            for (int o = 0; o < 8; o++) acc2[a][o] = 0.f;
        int i = t / 14, j = t % 14;
        int ylo = i / 2, yhi = min((i + 1) / 2, 6);
        int xlo = j / 2, xhi = min((j + 1) / 2, 6);
        for (int c = 0; c < 16; c++) {
            for (int y = ylo; y <= yhi; y++) {
                int ki = i - 2 * y + 1;
                for (int xx = xlo; xx <= xhi; xx++) {
                    int kj = j - 2 * xx + 1;
                    float u0 = d1s[0 * 784 + c * 49 + y * 7 + xx];
                    float u1 = d1s[1 * 784 + c * 49 + y * 7 + xx];
                    float u2 = d1s[2 * 784 + c * 49 + y * 7 + xx];
                    float u3 = d1s[3 * 784 + c * 49 + y * 7 + xx];
                    #pragma unroll
                    for (int o = 0; o < 8; o++) {
                        float wv = wd2s[((c * 8 + o) * 3 + ki) * 3 + kj];
                        acc2[0][o] += u0 * wv;
                        acc2[1][o] += u1 * wv;
                        acc2[2][o] += u2 * wv;
                        acc2[3][o] += u3 * wv;
                    }
                }
            }
        }
        #pragma unroll
        for (int o = 0; o < 8; o++) {
            float s = gd2[o] * rs;
            float bias = bd2[o] * s + btd2[o];
            #pragma unroll
            for (int a = 0; a < 4; a++)
                d2s[a * 1568 + o * 196 + t] = fmaxf(acc2[a][o] * s + bias, 0.f);
        }
    }
    __syncthreads();

    const float bb3 = bd3[0];
    for (int idx = t; idx < 3136; idx += 256) {
        int a = idx / 784, p = idx % 784, i = p / 28, j = p % 28;
        int ylo = i / 2, yhi = min((i + 1) / 2, 13);
        int xlo = j / 2, xhi = min((j + 1) / 2, 13);
        float acc3 = bb3;
        for (int c = 0; c < 8; c++) {
            for (int y = ylo; y <= yhi; y++) {
                int ki = i - 2 * y + 1;
                for (int xx = xlo; xx <= xhi; xx++) {
                    int kj = j - 2 * xx + 1;
                    acc3 += d2s[a * 1568 + c * 196 + y * 14 + xx] * wd3s[c * 9 + ki * 3 + kj];
                }
            }
        }
        out[(size_t)(b0 + a) * 784 + p] = 1.f / (1.f + expf(-acc3));
    }
}

// ---------------------------------------------------------------------------
extern "C" void kernel_launch(void* const* d_in, const int* in_sizes, int n_in,
                              void* d_out, int out_size)
{
    const float* x     = (const float*)d_in[0];
    const float* w1    = (const float*)d_in[1];
    const float* b1    = (const float*)d_in[2];
    const float* w2    = (const float*)d_in[3];
    const float* b2    = (const float*)d_in[4];
    const float* g2    = (const float*)d_in[5];
    const float* bt2   = (const float*)d_in[6];
    const float* w3    = (const float*)d_in[7];
    const float* b3    = (const float*)d_in[8];
    const float* proto = (const float*)d_in[9];
    const float* wup   = (const float*)d_in[10];
    const float* bup   = (const float*)d_in[11];
    const float* gup   = (const float*)d_in[12];
    const float* btup  = (const float*)d_in[13];
    const float* wd1   = (const float*)d_in[14];
    const float* bd1   = (const float*)d_in[15];
    const float* gd1   = (const float*)d_in[16];
    const float* btd1  = (const float*)d_in[17];
    const float* wd2   = (const float*)d_in[18];
    const float* bd2   = (const float*)d_in[19];
    const float* gd2   = (const float*)d_in[20];
    const float* btd2  = (const float*)d_in[21];
    const float* wd3   = (const float*)d_in[22];
    const float* bd3   = (const float*)d_in[23];

    float* out  = (float*)d_out;                 // (4096,1,28,28)
    float* minD = out + (size_t)NB * 784;        // (4096,512)

    prep_kernel<<<128, 256>>>(proto, w3, wd1);
    enc12_kernel<<<NB, 128>>>(x, w1, b1, w2, b2, g2, bt2);
    conv3_kernel<<<NB, 256>>>(b3);
    proto_kernel<<<NB, 512>>>(minD);

    dim3 gz(256 / 64, NB / 128);
    z_gemm_kernel<<<gz, 256>>>(proto);

    dim3 gu(6400 / 64, NB / 128);
    up_gemm_kernel<<<gu, 256>>>(wup, bup, gup, btup);

    size_t smem = (size_t)(25600 + 4608 + 3136 + 6272 + 1152 + 72) * sizeof(float);
    cudaFuncSetAttribute(dec_kernel, cudaFuncAttributeMaxDynamicSharedMemorySize, (int)smem);
    dec_kernel<<<NB / 4, 256, smem>>>(bd1, gd1, btd1,
                                      wd2, bd2, gd2, btd2,
                                      wd3, bd3, out);
}